// round 9
// baseline (speedup 1.0000x reference)
#include <cuda_runtime.h>
#include <cuda_bf16.h>
#include <cstdint>
#include <math.h>

#define BB   8
#define LL   4096
#define DMD  256
#define DI   384
#define DS   8
#define CHUNK 32
#define MTOK (BB*LL)          // 32768
#define NCHUNK (MTOK/CHUNK)   // 1024

// ---------------- scratch (device globals; no allocation) ----------------
__device__ __nv_bfloat16 g_xn  [MTOK * DMD];
__device__ float         g_xz  [MTOK * 2 * DI];   // silu(x_proj)|silu(z)
__device__ float         g_dt  [MTOK * DI];       // softplus(dt) directly from GEMM1
__device__ __nv_bfloat16 g_y   [MTOK * DI];
__device__ __nv_bfloat16 g_Wall[3 * DI * DMD];    // rows 0-767: Win[0:768]; rows 768-1151: W_fused
__device__ float         g_ball[3 * DI];          // b_in[0:768] | b_fused
__device__ __nv_bfloat16 g_Wout[DMD * DI];

// ---------------- helpers ----------------
__device__ __forceinline__ uint32_t smem_u32(const void* p) {
    uint32_t a;
    asm("{ .reg .u64 t; cvta.to.shared.u64 t, %1; cvt.u32.u64 %0, t; }" : "=r"(a) : "l"(p));
    return a;
}
__device__ __forceinline__ void cp16s(uint32_t s, const void* g) {
    asm volatile("cp.async.cg.shared.global [%0], [%1], 16;\n" :: "r"(s), "l"(g));
}
__device__ __forceinline__ void cp_commit() { asm volatile("cp.async.commit_group;\n"); }

// ---------------- prep: copy weights/bias, convert to bf16 ----------------
__global__ void cvt_w(const float* __restrict__ Win, const float* __restrict__ Wout,
                      const float* __restrict__ b_in)
{
    int i = blockIdx.x * 256 + threadIdx.x;
    if (i < 2 * DI * DMD) g_Wall[i] = __float2bfloat16(Win[i]);   // first 768 rows
    if (i < DMD * DI)     g_Wout[i] = __float2bfloat16(Wout[i]);
    if (i < 2 * DI)       g_ball[i] = b_in[i];
}

// ---------------- prep: W_fused = W_dt @ W_in[768:1152]  (384x256, fp32 -> bf16) ----
__global__ void __launch_bounds__(256)
wfuse_kernel(const float* __restrict__ Wdt, const float* __restrict__ Win)
{
    __shared__ float As[64][17];
    __shared__ float Bs[16][65];
    int by = blockIdx.y;        // i-tile (6)
    int bx = blockIdx.x;        // k-tile (4)
    int tid = threadIdx.x;
    int ty = tid >> 4, tx = tid & 15;
    float acc[4][4] = {};

    for (int kt = 0; kt < DI; kt += 16) {
        {
            int r = tid >> 2, c4 = (tid & 3) * 4;
            float4 v = *(const float4*)&Wdt[(by * 64 + r) * DI + kt + c4];
            As[r][c4] = v.x; As[r][c4 + 1] = v.y; As[r][c4 + 2] = v.z; As[r][c4 + 3] = v.w;
        }
        {
            int r = tid >> 4, c4 = (tid & 15) * 4;
            float4 v = *(const float4*)&Win[(2 * DI + kt + r) * DMD + bx * 64 + c4];
            Bs[r][c4] = v.x; Bs[r][c4 + 1] = v.y; Bs[r][c4 + 2] = v.z; Bs[r][c4 + 3] = v.w;
        }
        __syncthreads();
        #pragma unroll
        for (int k = 0; k < 16; k++) {
            float a[4], b[4];
            #pragma unroll
            for (int i = 0; i < 4; i++) a[i] = As[ty * 4 + i][k];
            #pragma unroll
            for (int j = 0; j < 4; j++) b[j] = Bs[k][tx * 4 + j];
            #pragma unroll
            for (int i = 0; i < 4; i++)
                #pragma unroll
                for (int j = 0; j < 4; j++) acc[i][j] = fmaf(a[i], b[j], acc[i][j]);
        }
        __syncthreads();
    }
    #pragma unroll
    for (int i = 0; i < 4; i++)
        #pragma unroll
        for (int j = 0; j < 4; j++)
            g_Wall[(2 * DI + by * 64 + ty * 4 + i) * DMD + bx * 64 + tx * 4 + j] =
                __float2bfloat16(acc[i][j]);
}

// ---------------- prep: b_fused = W_dt @ b_in[768:1152] + b_dt ----------------
__global__ void bfuse_kernel(const float* __restrict__ Wdt,
                             const float* __restrict__ b_in,
                             const float* __restrict__ b_dt)
{
    int i = threadIdx.x;          // 384 threads
    float s = b_dt[i];
    for (int j = 0; j < DI; j++) s = fmaf(Wdt[i * DI + j], b_in[2 * DI + j], s);
    g_ball[2 * DI + i] = s;
}

// ---------------- LayerNorm -> bf16 ----------------
__global__ void ln_kernel(const float* __restrict__ x,
                          const float* __restrict__ gamma,
                          const float* __restrict__ beta,
                          __nv_bfloat16* __restrict__ xn)
{
    int row = blockIdx.x;
    int t   = threadIdx.x;
    float v = x[(long)row * DMD + t];

    float s1 = v, s2 = v * v;
    #pragma unroll
    for (int o = 16; o; o >>= 1) {
        s1 += __shfl_xor_sync(0xffffffffu, s1, o);
        s2 += __shfl_xor_sync(0xffffffffu, s2, o);
    }
    __shared__ float red[16];
    int warp = t >> 5, lane = t & 31;
    if (lane == 0) { red[warp] = s1; red[8 + warp] = s2; }
    __syncthreads();
    if (t == 0) {
        float a = 0.f, b = 0.f;
        #pragma unroll
        for (int i = 0; i < 8; i++) { a += red[i]; b += red[8 + i]; }
        float mean = a * (1.0f / DMD);
        float var  = b * (1.0f / DMD) - mean * mean;
        red[0] = mean;
        red[8] = rsqrtf(var + 1e-5f);
    }
    __syncthreads();
    float mean = red[0], rstd = red[8];
    xn[(long)row * DMD + t] = __float2bfloat16((v - mean) * rstd * gamma[t] + beta[t]);
}

// ---------------- bf16 tensor-core GEMM ----------------
// Block 128x128, K-tile 64, 512 thr = 16 warps (4Mx4N), warp tile 32x32,
// NSTG=3 cp.async pipeline + fragment double buffering.

#define NSTG 3
#define PADK 72
#define TILE_B (128 * PADK * 2)
#define SMEM_G (2 * NSTG * TILE_B)     // 110592 B

__device__ __forceinline__ void ldsm4(uint32_t* r, uint32_t addr) {
    asm volatile("ldmatrix.sync.aligned.m8n8.x4.shared.b16 {%0,%1,%2,%3}, [%4];"
                 : "=r"(r[0]), "=r"(r[1]), "=r"(r[2]), "=r"(r[3]) : "r"(addr));
}
__device__ __forceinline__ void mma16816(float* d, const uint32_t* a, const uint32_t* b) {
    asm volatile(
        "mma.sync.aligned.m16n8k16.row.col.f32.bf16.bf16.f32 "
        "{%0,%1,%2,%3}, {%4,%5,%6,%7}, {%8,%9}, {%0,%1,%2,%3};\n"
        : "+f"(d[0]), "+f"(d[1]), "+f"(d[2]), "+f"(d[3])
        : "r"(a[0]), "r"(a[1]), "r"(a[2]), "r"(a[3]), "r"(b[0]), "r"(b[1]));
}

// EPI 0: GEMM1 -> n0<768: silu fp32 to Cf (ld 768); n0>=768: softplus fp32 to Cd (ld DI)
// EPI 2: fp32 + resid to Cf
template <int EPI>
__global__ void __launch_bounds__(512, 1)
bf_gemm(const __nv_bfloat16* __restrict__ A, int lda,
        const __nv_bfloat16* __restrict__ W, int ldb,
        const float* __restrict__ bias,
        float* __restrict__ Cf, int ldcf,
        float* __restrict__ Cd,
        int K,
        const float* __restrict__ resid)
{
    extern __shared__ char smem[];
    uint32_t sbA = smem_u32(smem);
    uint32_t sbB = sbA + NSTG * TILE_B;

    int tid = threadIdx.x, wid = tid >> 5, lane = tid & 31;
    int wm = wid & 3, wn = wid >> 2;
    int gid = lane >> 2, tig = lane & 3;
    int m0 = blockIdx.y * 128, n0 = blockIdx.x * 128;
    int KT = K / 64;

    const __nv_bfloat16* Ag = A + (long)m0 * lda;
    const __nv_bfloat16* Wg = W + (long)n0 * ldb;

    int lr0 = tid >> 3,          lk0 = (tid & 7) * 8;
    int lr1 = (tid + 512) >> 3,  lk1 = ((tid + 512) & 7) * 8;
    uint32_t so0 = (uint32_t)(lr0 * (PADK * 2) + lk0 * 2);
    uint32_t so1 = (uint32_t)(lr1 * (PADK * 2) + lk1 * 2);

    int arow = wm * 32 + (lane & 15);
    uint32_t aoff = (uint32_t)(arow * (PADK * 2) + ((lane >> 4) & 1) * 16);
    int grp = lane >> 3;
    int brow = wn * 32 + ((grp >> 1) * 8) + (lane & 7);
    uint32_t boff = (uint32_t)(brow * (PADK * 2) + (grp & 1) * 16);

    float acc[2][4][4];
    #pragma unroll
    for (int i = 0; i < 2; i++)
        #pragma unroll
        for (int j = 0; j < 4; j++)
            #pragma unroll
            for (int q = 0; q < 4; q++) acc[i][j][q] = 0.f;

    #pragma unroll
    for (int s = 0; s < NSTG - 1; s++) {
        cp16s(sbA + s * TILE_B + so0, Ag + (long)lr0 * lda + s * 64 + lk0);
        cp16s(sbA + s * TILE_B + so1, Ag + (long)lr1 * lda + s * 64 + lk1);
        cp16s(sbB + s * TILE_B + so0, Wg + (long)lr0 * ldb + s * 64 + lk0);
        cp16s(sbB + s * TILE_B + so1, Wg + (long)lr1 * ldb + s * 64 + lk1);
        cp_commit();
    }

    uint32_t af[2][2][4], bfr[2][4][2];

    for (int kt = 0; kt < KT; kt++) {
        asm volatile("cp.async.wait_group %0;" :: "n"(NSTG - 2));
        __syncthreads();

        int slot = kt % NSTG;
        uint32_t aS = sbA + slot * TILE_B;
        uint32_t bS = sbB + slot * TILE_B;

        {
            uint32_t t4[4];
            ldsm4(t4, bS + boff);
            bfr[0][0][0] = t4[0]; bfr[0][0][1] = t4[1];
            bfr[0][1][0] = t4[2]; bfr[0][1][1] = t4[3];
            ldsm4(t4, bS + boff + 16 * (PADK * 2));
            bfr[0][2][0] = t4[0]; bfr[0][2][1] = t4[1];
            bfr[0][3][0] = t4[2]; bfr[0][3][1] = t4[3];
            ldsm4(af[0][0], aS + aoff);
            ldsm4(af[0][1], aS + aoff + 16 * (PADK * 2));
        }

        int nk = kt + NSTG - 1;
        if (nk < KT) {
            int s = nk % NSTG;
            cp16s(sbA + s * TILE_B + so0, Ag + (long)lr0 * lda + nk * 64 + lk0);
            cp16s(sbA + s * TILE_B + so1, Ag + (long)lr1 * lda + nk * 64 + lk1);
            cp16s(sbB + s * TILE_B + so0, Wg + (long)lr0 * ldb + nk * 64 + lk0);
            cp16s(sbB + s * TILE_B + so1, Wg + (long)lr1 * ldb + nk * 64 + lk1);
        }
        cp_commit();

        #pragma unroll
        for (int kk = 0; kk < 4; kk++) {
            int cur = kk & 1, nxt = cur ^ 1;
            if (kk < 3) {
                int kb = (kk + 1) * 32;
                uint32_t t4[4];
                ldsm4(t4, bS + boff + kb);
                bfr[nxt][0][0] = t4[0]; bfr[nxt][0][1] = t4[1];
                bfr[nxt][1][0] = t4[2]; bfr[nxt][1][1] = t4[3];
                ldsm4(t4, bS + boff + 16 * (PADK * 2) + kb);
                bfr[nxt][2][0] = t4[0]; bfr[nxt][2][1] = t4[1];
                bfr[nxt][3][0] = t4[2]; bfr[nxt][3][1] = t4[3];
                ldsm4(af[nxt][0], aS + aoff + kb);
                ldsm4(af[nxt][1], aS + aoff + 16 * (PADK * 2) + kb);
            }
            #pragma unroll
            for (int ma = 0; ma < 2; ma++)
                #pragma unroll
                for (int na = 0; na < 4; na++)
                    mma16816(acc[ma][na], af[cur][ma], bfr[cur][na]);
        }
    }

    // epilogue
    bool dreg = (EPI == 0) && (n0 >= 2 * DI);
    #pragma unroll
    for (int ma = 0; ma < 2; ma++) {
        #pragma unroll
        for (int na = 0; na < 4; na++) {
            int col = n0 + wn * 32 + na * 8 + tig * 2;
            float b0 = bias[col], b1 = bias[col + 1];
            #pragma unroll
            for (int half = 0; half < 2; half++) {
                int row = m0 + wm * 32 + ma * 16 + gid + half * 8;
                float v0 = acc[ma][na][half * 2 + 0] + b0;
                float v1 = acc[ma][na][half * 2 + 1] + b1;
                if (EPI == 0) {
                    if (!dreg) {
                        v0 = v0 / (1.f + __expf(-v0));
                        v1 = v1 / (1.f + __expf(-v1));
                        *(float2*)&Cf[(long)row * ldcf + col] = make_float2(v0, v1);
                    } else {
                        v0 = fmaxf(v0, 0.f) + log1pf(__expf(-fabsf(v0)));
                        v1 = fmaxf(v1, 0.f) + log1pf(__expf(-fabsf(v1)));
                        *(float2*)&Cd[(long)row * DI + (col - 2 * DI)] = make_float2(v0, v1);
                    }
                } else {
                    v0 += resid[(long)row * DMD + col];
                    v1 += resid[(long)row * DMD + col + 1];
                    *(float2*)&Cf[(long)row * ldcf + col] = make_float2(v0, v1);
                }
            }
        }
    }
}

// ---------------- chunked selective scan + gating ----------------
__global__ void __launch_bounds__(384)
scan_kernel(const float* __restrict__ xz,
            const float* __restrict__ dt,
            const float* __restrict__ A_log,
            const float* __restrict__ D_vec,
            __nv_bfloat16* __restrict__ y)
{
    __shared__ float a2[DI * DS];
    int tid = threadIdx.x;
    for (int i = tid; i < DI * DS; i += DI)
        a2[i] = -expf(A_log[i]) * 1.4426950408889634f;
    __syncthreads();

    int di = tid;
    float av[DS];
    #pragma unroll
    for (int s = 0; s < DS; s++) av[s] = a2[di * DS + s];
    float dval = D_vec[di];

    long row0 = (long)blockIdx.x * CHUNK;
    float h[DS];
    #pragma unroll
    for (int s = 0; s < DS; s++) h[s] = 0.f;

    #pragma unroll 4
    for (int t = 0; t < CHUNK; t++) {
        long m  = row0 + t;
        float dtv = dt[m * DI + di];
        float xv  = xz[m * (2 * DI) + di];
        float zv  = xz[m * (2 * DI) + DI + di];
        float ys = 0.f;
        #pragma unroll
        for (int s = 0; s < DS; s++) {
            h[s] = fmaf(h[s], exp2f(dtv * av[s]), xv);
            ys += h[s];
        }
        y[m * DI + di] = __float2bfloat16(fmaf(ys, zv, xv * dval));
    }
}

// ---------------- launch ----------------
extern "C" void kernel_launch(void* const* d_in, const int* in_sizes, int n_in,
                              void* d_out, int out_size)
{
    const float* x     = (const float*)d_in[0];
    const float* gamma = (const float*)d_in[1];
    const float* beta  = (const float*)d_in[2];
    const float* W_in  = (const float*)d_in[3];
    const float* b_in  = (const float*)d_in[4];
    const float* W_dt  = (const float*)d_in[5];
    const float* b_dt  = (const float*)d_in[6];
    const float* A_log = (const float*)d_in[7];
    const float* D_vec = (const float*)d_in[8];
    const float* W_out = (const float*)d_in[9];
    const float* b_out = (const float*)d_in[10];
    float* out = (float*)d_out;

    __nv_bfloat16 *xn, *yb, *wall, *wout;
    float *xz, *dtb, *ball;
    cudaGetSymbolAddress((void**)&xn,   g_xn);
    cudaGetSymbolAddress((void**)&xz,   g_xz);
    cudaGetSymbolAddress((void**)&dtb,  g_dt);
    cudaGetSymbolAddress((void**)&yb,   g_y);
    cudaGetSymbolAddress((void**)&wall, g_Wall);
    cudaGetSymbolAddress((void**)&ball, g_ball);
    cudaGetSymbolAddress((void**)&wout, g_Wout);

    cudaFuncSetAttribute(bf_gemm<0>, cudaFuncAttributeMaxDynamicSharedMemorySize, SMEM_G);
    cudaFuncSetAttribute(bf_gemm<2>, cudaFuncAttributeMaxDynamicSharedMemorySize, SMEM_G);

    // 0) prep: copy first 768 weight rows + Wout + biases; build fused W/b
    cvt_w<<<(2 * DI * DMD + 255) / 256, 256>>>(W_in, W_out, b_in);
    wfuse_kernel<<<dim3(4, 6), 256>>>(W_dt, W_in);
    bfuse_kernel<<<1, DI>>>(W_dt, b_in, b_dt);

    // 1) LayerNorm -> bf16
    ln_kernel<<<MTOK, DMD>>>(x, gamma, beta, xn);

    // 2) GEMM1: cols 0-767 -> silu fp32 xz ; cols 768-1151 -> softplus fp32 dt
    bf_gemm<0><<<dim3(9, MTOK / 128), 512, SMEM_G>>>(
        xn, DMD, wall, DMD, ball, xz, 2 * DI, dtb, DMD, nullptr);

    // 3) chunked scan + gating -> y (bf16)
    scan_kernel<<<NCHUNK, DI>>>(xz, dtb, A_log, D_vec, yb);

    // 4) GEMM3: out = y @ W_out^T + b_out + residual
    bf_gemm<2><<<dim3(2, MTOK / 128), 512, SMEM_G>>>(
        yb, DI, wout, DI, b_out, out, DMD, nullptr, DI, x);
}

// round 10
// speedup vs baseline: 1.3301x; 1.3301x over previous
#include <cuda_runtime.h>
#include <cuda_bf16.h>
#include <cstdint>
#include <math.h>

#define BB   8
#define LL   4096
#define DMD  256
#define DI   384
#define DS   8
#define CHUNK 32
#define MTOK (BB*LL)          // 32768
#define NCHUNK (MTOK/CHUNK)   // 1024

// ---------------- scratch (device globals; no allocation) ----------------
__device__ __nv_bfloat16 g_xn  [MTOK * DMD];
__device__ float         g_xz  [MTOK * 2 * DI];   // silu(x_proj)|silu(z)
__device__ float         g_dt  [MTOK * DI];       // softplus(dt) directly from GEMM1
__device__ __nv_bfloat16 g_y   [MTOK * DI];
__device__ __nv_bfloat16 g_Wall[3 * DI * DMD];    // rows 0-767: Win[0:768]; rows 768-1151: W_fused
__device__ float         g_ball[3 * DI];          // b_in[0:768] | b_fused
__device__ __nv_bfloat16 g_Wout[DMD * DI];

// ---------------- helpers ----------------
__device__ __forceinline__ uint32_t smem_u32(const void* p) {
    uint32_t a;
    asm("{ .reg .u64 t; cvta.to.shared.u64 t, %1; cvt.u32.u64 %0, t; }" : "=r"(a) : "l"(p));
    return a;
}
__device__ __forceinline__ void cp16s(uint32_t s, const void* g) {
    asm volatile("cp.async.cg.shared.global [%0], [%1], 16;\n" :: "r"(s), "l"(g));
}
__device__ __forceinline__ void cp_commit() { asm volatile("cp.async.commit_group;\n"); }

// ---------------- prep: copy weights/bias, convert to bf16 ----------------
__global__ void cvt_w(const float* __restrict__ Win, const float* __restrict__ Wout,
                      const float* __restrict__ b_in)
{
    int i = blockIdx.x * 256 + threadIdx.x;
    if (i < 2 * DI * DMD) g_Wall[i] = __float2bfloat16(Win[i]);   // first 768 rows
    if (i < DMD * DI)     g_Wout[i] = __float2bfloat16(Wout[i]);
    if (i < 2 * DI)       g_ball[i] = b_in[i];
}

// ---------------- prep: W_fused = W_dt @ W_in[768:1152]  (384x256) ----------------
__global__ void __launch_bounds__(256)
wfuse_kernel(const float* __restrict__ Wdt, const float* __restrict__ Win)
{
    __shared__ float As[64][17];
    __shared__ float Bs[16][65];
    int by = blockIdx.y;        // i-tile (6)
    int bx = blockIdx.x;        // k-tile (4)
    int tid = threadIdx.x;
    int ty = tid >> 4, tx = tid & 15;
    float acc[4][4] = {};

    for (int kt = 0; kt < DI; kt += 16) {
        {
            int r = tid >> 2, c4 = (tid & 3) * 4;
            float4 v = *(const float4*)&Wdt[(by * 64 + r) * DI + kt + c4];
            As[r][c4] = v.x; As[r][c4 + 1] = v.y; As[r][c4 + 2] = v.z; As[r][c4 + 3] = v.w;
        }
        {
            int r = tid >> 4, c4 = (tid & 15) * 4;
            float4 v = *(const float4*)&Win[(2 * DI + kt + r) * DMD + bx * 64 + c4];
            Bs[r][c4] = v.x; Bs[r][c4 + 1] = v.y; Bs[r][c4 + 2] = v.z; Bs[r][c4 + 3] = v.w;
        }
        __syncthreads();
        #pragma unroll
        for (int k = 0; k < 16; k++) {
            float a[4], b[4];
            #pragma unroll
            for (int i = 0; i < 4; i++) a[i] = As[ty * 4 + i][k];
            #pragma unroll
            for (int j = 0; j < 4; j++) b[j] = Bs[k][tx * 4 + j];
            #pragma unroll
            for (int i = 0; i < 4; i++)
                #pragma unroll
                for (int j = 0; j < 4; j++) acc[i][j] = fmaf(a[i], b[j], acc[i][j]);
        }
        __syncthreads();
    }
    #pragma unroll
    for (int i = 0; i < 4; i++)
        #pragma unroll
        for (int j = 0; j < 4; j++)
            g_Wall[(2 * DI + by * 64 + ty * 4 + i) * DMD + bx * 64 + tx * 4 + j] =
                __float2bfloat16(acc[i][j]);
}

// ---------------- prep: b_fused = W_dt @ b_in[768:1152] + b_dt ----------------
// one block per output row; coalesced row reads + warp reduction
__global__ void __launch_bounds__(128)
bfuse_kernel(const float* __restrict__ Wdt,
             const float* __restrict__ b_in,
             const float* __restrict__ b_dt)
{
    int i = blockIdx.x;           // 384 blocks
    int t = threadIdx.x;          // 128 threads
    float s = 0.f;
    #pragma unroll
    for (int j = t; j < DI; j += 128)
        s = fmaf(Wdt[i * DI + j], b_in[2 * DI + j], s);
    #pragma unroll
    for (int o = 16; o; o >>= 1) s += __shfl_xor_sync(0xffffffffu, s, o);
    __shared__ float red[4];
    if ((t & 31) == 0) red[t >> 5] = s;
    __syncthreads();
    if (t == 0)
        g_ball[2 * DI + i] = red[0] + red[1] + red[2] + red[3] + b_dt[i];
}

// ---------------- LayerNorm -> bf16 (warp per row) ----------------
__global__ void __launch_bounds__(256)
ln_kernel(const float* __restrict__ x,
          const float* __restrict__ gamma,
          const float* __restrict__ beta,
          __nv_bfloat16* __restrict__ xn)
{
    int warp = threadIdx.x >> 5, lane = threadIdx.x & 31;
    long row = (long)blockIdx.x * 8 + warp;
    const float* xr = x + row * DMD;

    float4 v0 = *(const float4*)(xr + lane * 8);
    float4 v1 = *(const float4*)(xr + lane * 8 + 4);

    float s1 = v0.x + v0.y + v0.z + v0.w + v1.x + v1.y + v1.z + v1.w;
    float s2 = v0.x*v0.x + v0.y*v0.y + v0.z*v0.z + v0.w*v0.w
             + v1.x*v1.x + v1.y*v1.y + v1.z*v1.z + v1.w*v1.w;
    #pragma unroll
    for (int o = 16; o; o >>= 1) {
        s1 += __shfl_xor_sync(0xffffffffu, s1, o);
        s2 += __shfl_xor_sync(0xffffffffu, s2, o);
    }
    float mean = s1 * (1.0f / DMD);
    float rstd = rsqrtf(s2 * (1.0f / DMD) - mean * mean + 1e-5f);

    const float4 g0 = *(const float4*)(gamma + lane * 8);
    const float4 g1 = *(const float4*)(gamma + lane * 8 + 4);
    const float4 be0 = *(const float4*)(beta + lane * 8);
    const float4 be1 = *(const float4*)(beta + lane * 8 + 4);

    __nv_bfloat16 o[8];
    o[0] = __float2bfloat16((v0.x - mean) * rstd * g0.x + be0.x);
    o[1] = __float2bfloat16((v0.y - mean) * rstd * g0.y + be0.y);
    o[2] = __float2bfloat16((v0.z - mean) * rstd * g0.z + be0.z);
    o[3] = __float2bfloat16((v0.w - mean) * rstd * g0.w + be0.w);
    o[4] = __float2bfloat16((v1.x - mean) * rstd * g1.x + be1.x);
    o[5] = __float2bfloat16((v1.y - mean) * rstd * g1.y + be1.y);
    o[6] = __float2bfloat16((v1.z - mean) * rstd * g1.z + be1.z);
    o[7] = __float2bfloat16((v1.w - mean) * rstd * g1.w + be1.w);
    *(uint4*)(xn + row * DMD + lane * 8) = *(uint4*)o;
}

// ---------------- bf16 tensor-core GEMM ----------------
// Block 128x128, K-tile 64, 512 thr = 16 warps (4Mx4N), warp tile 32x32,
// NSTG=3 cp.async pipeline + fragment double buffering.

#define NSTG 3
#define PADK 72
#define TILE_B (128 * PADK * 2)
#define SMEM_G (2 * NSTG * TILE_B)     // 110592 B

__device__ __forceinline__ void ldsm4(uint32_t* r, uint32_t addr) {
    asm volatile("ldmatrix.sync.aligned.m8n8.x4.shared.b16 {%0,%1,%2,%3}, [%4];"
                 : "=r"(r[0]), "=r"(r[1]), "=r"(r[2]), "=r"(r[3]) : "r"(addr));
}
__device__ __forceinline__ void mma16816(float* d, const uint32_t* a, const uint32_t* b) {
    asm volatile(
        "mma.sync.aligned.m16n8k16.row.col.f32.bf16.bf16.f32 "
        "{%0,%1,%2,%3}, {%4,%5,%6,%7}, {%8,%9}, {%0,%1,%2,%3};\n"
        : "+f"(d[0]), "+f"(d[1]), "+f"(d[2]), "+f"(d[3])
        : "r"(a[0]), "r"(a[1]), "r"(a[2]), "r"(a[3]), "r"(b[0]), "r"(b[1]));
}

// EPI 0: GEMM1 -> n0<768: silu fp32 to Cf (ld 768); n0>=768: softplus fp32 to Cd (ld DI)
// EPI 2: fp32 + resid to Cf
template <int EPI>
__global__ void __launch_bounds__(512, 1)
bf_gemm(const __nv_bfloat16* __restrict__ A, int lda,
        const __nv_bfloat16* __restrict__ W, int ldb,
        const float* __restrict__ bias,
        float* __restrict__ Cf, int ldcf,
        float* __restrict__ Cd,
        int K,
        const float* __restrict__ resid)
{
    extern __shared__ char smem[];
    uint32_t sbA = smem_u32(smem);
    uint32_t sbB = sbA + NSTG * TILE_B;

    int tid = threadIdx.x, wid = tid >> 5, lane = tid & 31;
    int wm = wid & 3, wn = wid >> 2;
    int gid = lane >> 2, tig = lane & 3;
    int m0 = blockIdx.y * 128, n0 = blockIdx.x * 128;
    int KT = K / 64;

    const __nv_bfloat16* Ag = A + (long)m0 * lda;
    const __nv_bfloat16* Wg = W + (long)n0 * ldb;

    int lr0 = tid >> 3,          lk0 = (tid & 7) * 8;
    int lr1 = (tid + 512) >> 3,  lk1 = ((tid + 512) & 7) * 8;
    uint32_t so0 = (uint32_t)(lr0 * (PADK * 2) + lk0 * 2);
    uint32_t so1 = (uint32_t)(lr1 * (PADK * 2) + lk1 * 2);

    int arow = wm * 32 + (lane & 15);
    uint32_t aoff = (uint32_t)(arow * (PADK * 2) + ((lane >> 4) & 1) * 16);
    int grp = lane >> 3;
    int brow = wn * 32 + ((grp >> 1) * 8) + (lane & 7);
    uint32_t boff = (uint32_t)(brow * (PADK * 2) + (grp & 1) * 16);

    float acc[2][4][4];
    #pragma unroll
    for (int i = 0; i < 2; i++)
        #pragma unroll
        for (int j = 0; j < 4; j++)
            #pragma unroll
            for (int q = 0; q < 4; q++) acc[i][j][q] = 0.f;

    #pragma unroll
    for (int s = 0; s < NSTG - 1; s++) {
        cp16s(sbA + s * TILE_B + so0, Ag + (long)lr0 * lda + s * 64 + lk0);
        cp16s(sbA + s * TILE_B + so1, Ag + (long)lr1 * lda + s * 64 + lk1);
        cp16s(sbB + s * TILE_B + so0, Wg + (long)lr0 * ldb + s * 64 + lk0);
        cp16s(sbB + s * TILE_B + so1, Wg + (long)lr1 * ldb + s * 64 + lk1);
        cp_commit();
    }

    uint32_t af[2][2][4], bfr[2][4][2];

    for (int kt = 0; kt < KT; kt++) {
        asm volatile("cp.async.wait_group %0;" :: "n"(NSTG - 2));
        __syncthreads();

        int slot = kt % NSTG;
        uint32_t aS = sbA + slot * TILE_B;
        uint32_t bS = sbB + slot * TILE_B;

        {
            uint32_t t4[4];
            ldsm4(t4, bS + boff);
            bfr[0][0][0] = t4[0]; bfr[0][0][1] = t4[1];
            bfr[0][1][0] = t4[2]; bfr[0][1][1] = t4[3];
            ldsm4(t4, bS + boff + 16 * (PADK * 2));
            bfr[0][2][0] = t4[0]; bfr[0][2][1] = t4[1];
            bfr[0][3][0] = t4[2]; bfr[0][3][1] = t4[3];
            ldsm4(af[0][0], aS + aoff);
            ldsm4(af[0][1], aS + aoff + 16 * (PADK * 2));
        }

        int nk = kt + NSTG - 1;
        if (nk < KT) {
            int s = nk % NSTG;
            cp16s(sbA + s * TILE_B + so0, Ag + (long)lr0 * lda + nk * 64 + lk0);
            cp16s(sbA + s * TILE_B + so1, Ag + (long)lr1 * lda + nk * 64 + lk1);
            cp16s(sbB + s * TILE_B + so0, Wg + (long)lr0 * ldb + nk * 64 + lk0);
            cp16s(sbB + s * TILE_B + so1, Wg + (long)lr1 * ldb + nk * 64 + lk1);
        }
        cp_commit();

        #pragma unroll
        for (int kk = 0; kk < 4; kk++) {
            int cur = kk & 1, nxt = cur ^ 1;
            if (kk < 3) {
                int kb = (kk + 1) * 32;
                uint32_t t4[4];
                ldsm4(t4, bS + boff + kb);
                bfr[nxt][0][0] = t4[0]; bfr[nxt][0][1] = t4[1];
                bfr[nxt][1][0] = t4[2]; bfr[nxt][1][1] = t4[3];
                ldsm4(t4, bS + boff + 16 * (PADK * 2) + kb);
                bfr[nxt][2][0] = t4[0]; bfr[nxt][2][1] = t4[1];
                bfr[nxt][3][0] = t4[2]; bfr[nxt][3][1] = t4[3];
                ldsm4(af[nxt][0], aS + aoff + kb);
                ldsm4(af[nxt][1], aS + aoff + 16 * (PADK * 2) + kb);
            }
            #pragma unroll
            for (int ma = 0; ma < 2; ma++)
                #pragma unroll
                for (int na = 0; na < 4; na++)
                    mma16816(acc[ma][na], af[cur][ma], bfr[cur][na]);
        }
    }

    // epilogue
    bool dreg = (EPI == 0) && (n0 >= 2 * DI);
    #pragma unroll
    for (int ma = 0; ma < 2; ma++) {
        #pragma unroll
        for (int na = 0; na < 4; na++) {
            int col = n0 + wn * 32 + na * 8 + tig * 2;
            float b0 = bias[col], b1 = bias[col + 1];
            #pragma unroll
            for (int half = 0; half < 2; half++) {
                int row = m0 + wm * 32 + ma * 16 + gid + half * 8;
                float v0 = acc[ma][na][half * 2 + 0] + b0;
                float v1 = acc[ma][na][half * 2 + 1] + b1;
                if (EPI == 0) {
                    if (!dreg) {
                        v0 = v0 / (1.f + __expf(-v0));
                        v1 = v1 / (1.f + __expf(-v1));
                        *(float2*)&Cf[(long)row * ldcf + col] = make_float2(v0, v1);
                    } else {
                        v0 = fmaxf(v0, 0.f) + log1pf(__expf(-fabsf(v0)));
                        v1 = fmaxf(v1, 0.f) + log1pf(__expf(-fabsf(v1)));
                        *(float2*)&Cd[(long)row * DI + (col - 2 * DI)] = make_float2(v0, v1);
                    }
                } else {
                    v0 += resid[(long)row * DMD + col];
                    v1 += resid[(long)row * DMD + col + 1];
                    *(float2*)&Cf[(long)row * ldcf + col] = make_float2(v0, v1);
                }
            }
        }
    }
}

// ---------------- chunked selective scan + gating ----------------
__global__ void __launch_bounds__(384)
scan_kernel(const float* __restrict__ xz,
            const float* __restrict__ dt,
            const float* __restrict__ A_log,
            const float* __restrict__ D_vec,
            __nv_bfloat16* __restrict__ y)
{
    __shared__ float a2[DI * DS];
    int tid = threadIdx.x;
    for (int i = tid; i < DI * DS; i += DI)
        a2[i] = -expf(A_log[i]) * 1.4426950408889634f;
    __syncthreads();

    int di = tid;
    float av[DS];
    #pragma unroll
    for (int s = 0; s < DS; s++) av[s] = a2[di * DS + s];
    float dval = D_vec[di];

    long row0 = (long)blockIdx.x * CHUNK;
    float h[DS];
    #pragma unroll
    for (int s = 0; s < DS; s++) h[s] = 0.f;

    #pragma unroll 4
    for (int t = 0; t < CHUNK; t++) {
        long m  = row0 + t;
        float dtv = dt[m * DI + di];
        float xv  = xz[m * (2 * DI) + di];
        float zv  = xz[m * (2 * DI) + DI + di];
        float ys = 0.f;
        #pragma unroll
        for (int s = 0; s < DS; s++) {
            h[s] = fmaf(h[s], exp2f(dtv * av[s]), xv);
            ys += h[s];
        }
        y[m * DI + di] = __float2bfloat16(fmaf(ys, zv, xv * dval));
    }
}

// ---------------- launch ----------------
extern "C" void kernel_launch(void* const* d_in, const int* in_sizes, int n_in,
                              void* d_out, int out_size)
{
    const float* x     = (const float*)d_in[0];
    const float* gamma = (const float*)d_in[1];
    const float* beta  = (const float*)d_in[2];
    const float* W_in  = (const float*)d_in[3];
    const float* b_in  = (const float*)d_in[4];
    const float* W_dt  = (const float*)d_in[5];
    const float* b_dt  = (const float*)d_in[6];
    const float* A_log = (const float*)d_in[7];
    const float* D_vec = (const float*)d_in[8];
    const float* W_out = (const float*)d_in[9];
    const float* b_out = (const float*)d_in[10];
    float* out = (float*)d_out;

    __nv_bfloat16 *xn, *yb, *wall, *wout;
    float *xz, *dtb, *ball;
    cudaGetSymbolAddress((void**)&xn,   g_xn);
    cudaGetSymbolAddress((void**)&xz,   g_xz);
    cudaGetSymbolAddress((void**)&dtb,  g_dt);
    cudaGetSymbolAddress((void**)&yb,   g_y);
    cudaGetSymbolAddress((void**)&wall, g_Wall);
    cudaGetSymbolAddress((void**)&ball, g_ball);
    cudaGetSymbolAddress((void**)&wout, g_Wout);

    cudaFuncSetAttribute(bf_gemm<0>, cudaFuncAttributeMaxDynamicSharedMemorySize, SMEM_G);
    cudaFuncSetAttribute(bf_gemm<2>, cudaFuncAttributeMaxDynamicSharedMemorySize, SMEM_G);

    // 0) prep (fast, parallel): copy/convert weights; build fused W/b
    cvt_w<<<(2 * DI * DMD + 255) / 256, 256>>>(W_in, W_out, b_in);
    wfuse_kernel<<<dim3(4, 6), 256>>>(W_dt, W_in);
    bfuse_kernel<<<DI, 128>>>(W_dt, b_in, b_dt);

    // 1) LayerNorm -> bf16 (warp per row)
    ln_kernel<<<MTOK / 8, 256>>>(x, gamma, beta, xn);

    // 2) GEMM1: cols 0-767 -> silu fp32 xz ; cols 768-1151 -> softplus fp32 dt
    bf_gemm<0><<<dim3(9, MTOK / 128), 512, SMEM_G>>>(
        xn, DMD, wall, DMD, ball, xz, 2 * DI, dtb, DMD, nullptr);

    // 3) chunked scan + gating -> y (bf16)
    scan_kernel<<<NCHUNK, DI>>>(xz, dtb, A_log, D_vec, yb);

    // 4) GEMM3: out = y @ W_out^T + b_out + residual
    bf_gemm<2><<<dim3(2, MTOK / 128), 512, SMEM_G>>>(
        yb, DI, wout, DI, b_out, out, DMD, nullptr, DI, x);
}

// round 11
// speedup vs baseline: 1.3862x; 1.0422x over previous
#include <cuda_runtime.h>
#include <cuda_bf16.h>
#include <cstdint>
#include <math.h>

#define BB   8
#define LL   4096
#define DMD  256
#define DI   384
#define DS   8
#define CHUNK 32
#define MTOK (BB*LL)          // 32768
#define NCHUNK (MTOK/CHUNK)   // 1024

// ---------------- scratch (device globals; no allocation) ----------------
__device__ __nv_bfloat16 g_xn  [MTOK * DMD];
__device__ __nv_bfloat16 g_xzb [MTOK * 2 * DI];   // bf16: silu(x_proj)|silu(z)
__device__ float         g_dt  [MTOK * DI];       // softplus(dt) fp32
__device__ __nv_bfloat16 g_y   [MTOK * DI];
__device__ __nv_bfloat16 g_Wall[3 * DI * DMD];    // rows 0-767: Win[0:768]; rows 768-1151: W_fused
__device__ float         g_ball[3 * DI];          // b_in[0:768] | b_fused
__device__ __nv_bfloat16 g_Wout[DMD * DI];

// ---------------- helpers ----------------
__device__ __forceinline__ uint32_t smem_u32(const void* p) {
    uint32_t a;
    asm("{ .reg .u64 t; cvta.to.shared.u64 t, %1; cvt.u32.u64 %0, t; }" : "=r"(a) : "l"(p));
    return a;
}
__device__ __forceinline__ void cp16s(uint32_t s, const void* g) {
    asm volatile("cp.async.cg.shared.global [%0], [%1], 16;\n" :: "r"(s), "l"(g));
}
__device__ __forceinline__ void cp_commit() { asm volatile("cp.async.commit_group;\n"); }

// ---------------- prep: copy weights/bias, convert to bf16 ----------------
__global__ void cvt_w(const float* __restrict__ Win, const float* __restrict__ Wout,
                      const float* __restrict__ b_in)
{
    int i = blockIdx.x * 256 + threadIdx.x;
    if (i < 2 * DI * DMD) g_Wall[i] = __float2bfloat16(Win[i]);
    if (i < DMD * DI)     g_Wout[i] = __float2bfloat16(Wout[i]);
    if (i < 2 * DI)       g_ball[i] = b_in[i];
}

// ---------------- prep: W_fused = W_dt @ W_in[768:1152]  (384x256) ----------------
__global__ void __launch_bounds__(256)
wfuse_kernel(const float* __restrict__ Wdt, const float* __restrict__ Win)
{
    __shared__ float As[64][17];
    __shared__ float Bs[16][65];
    int by = blockIdx.y;
    int bx = blockIdx.x;
    int tid = threadIdx.x;
    int ty = tid >> 4, tx = tid & 15;
    float acc[4][4] = {};

    for (int kt = 0; kt < DI; kt += 16) {
        {
            int r = tid >> 2, c4 = (tid & 3) * 4;
            float4 v = *(const float4*)&Wdt[(by * 64 + r) * DI + kt + c4];
            As[r][c4] = v.x; As[r][c4 + 1] = v.y; As[r][c4 + 2] = v.z; As[r][c4 + 3] = v.w;
        }
        {
            int r = tid >> 4, c4 = (tid & 15) * 4;
            float4 v = *(const float4*)&Win[(2 * DI + kt + r) * DMD + bx * 64 + c4];
            Bs[r][c4] = v.x; Bs[r][c4 + 1] = v.y; Bs[r][c4 + 2] = v.z; Bs[r][c4 + 3] = v.w;
        }
        __syncthreads();
        #pragma unroll
        for (int k = 0; k < 16; k++) {
            float a[4], b[4];
            #pragma unroll
            for (int i = 0; i < 4; i++) a[i] = As[ty * 4 + i][k];
            #pragma unroll
            for (int j = 0; j < 4; j++) b[j] = Bs[k][tx * 4 + j];
            #pragma unroll
            for (int i = 0; i < 4; i++)
                #pragma unroll
                for (int j = 0; j < 4; j++) acc[i][j] = fmaf(a[i], b[j], acc[i][j]);
        }
        __syncthreads();
    }
    #pragma unroll
    for (int i = 0; i < 4; i++)
        #pragma unroll
        for (int j = 0; j < 4; j++)
            g_Wall[(2 * DI + by * 64 + ty * 4 + i) * DMD + bx * 64 + tx * 4 + j] =
                __float2bfloat16(acc[i][j]);
}

// ---------------- prep: b_fused = W_dt @ b_in[768:1152] + b_dt ----------------
__global__ void __launch_bounds__(128)
bfuse_kernel(const float* __restrict__ Wdt,
             const float* __restrict__ b_in,
             const float* __restrict__ b_dt)
{
    int i = blockIdx.x;
    int t = threadIdx.x;
    float s = 0.f;
    #pragma unroll
    for (int j = t; j < DI; j += 128)
        s = fmaf(Wdt[i * DI + j], b_in[2 * DI + j], s);
    #pragma unroll
    for (int o = 16; o; o >>= 1) s += __shfl_xor_sync(0xffffffffu, s, o);
    __shared__ float red[4];
    if ((t & 31) == 0) red[t >> 5] = s;
    __syncthreads();
    if (t == 0)
        g_ball[2 * DI + i] = red[0] + red[1] + red[2] + red[3] + b_dt[i];
}

// ---------------- LayerNorm -> bf16 (warp per row) ----------------
__global__ void __launch_bounds__(256)
ln_kernel(const float* __restrict__ x,
          const float* __restrict__ gamma,
          const float* __restrict__ beta,
          __nv_bfloat16* __restrict__ xn)
{
    int warp = threadIdx.x >> 5, lane = threadIdx.x & 31;
    long row = (long)blockIdx.x * 8 + warp;
    const float* xr = x + row * DMD;

    float4 v0 = *(const float4*)(xr + lane * 8);
    float4 v1 = *(const float4*)(xr + lane * 8 + 4);

    float s1 = v0.x + v0.y + v0.z + v0.w + v1.x + v1.y + v1.z + v1.w;
    float s2 = v0.x*v0.x + v0.y*v0.y + v0.z*v0.z + v0.w*v0.w
             + v1.x*v1.x + v1.y*v1.y + v1.z*v1.z + v1.w*v1.w;
    #pragma unroll
    for (int o = 16; o; o >>= 1) {
        s1 += __shfl_xor_sync(0xffffffffu, s1, o);
        s2 += __shfl_xor_sync(0xffffffffu, s2, o);
    }
    float mean = s1 * (1.0f / DMD);
    float rstd = rsqrtf(s2 * (1.0f / DMD) - mean * mean + 1e-5f);

    const float4 g0 = *(const float4*)(gamma + lane * 8);
    const float4 g1 = *(const float4*)(gamma + lane * 8 + 4);
    const float4 be0 = *(const float4*)(beta + lane * 8);
    const float4 be1 = *(const float4*)(beta + lane * 8 + 4);

    __nv_bfloat16 o[8];
    o[0] = __float2bfloat16((v0.x - mean) * rstd * g0.x + be0.x);
    o[1] = __float2bfloat16((v0.y - mean) * rstd * g0.y + be0.y);
    o[2] = __float2bfloat16((v0.z - mean) * rstd * g0.z + be0.z);
    o[3] = __float2bfloat16((v0.w - mean) * rstd * g0.w + be0.w);
    o[4] = __float2bfloat16((v1.x - mean) * rstd * g1.x + be1.x);
    o[5] = __float2bfloat16((v1.y - mean) * rstd * g1.y + be1.y);
    o[6] = __float2bfloat16((v1.z - mean) * rstd * g1.z + be1.z);
    o[7] = __float2bfloat16((v1.w - mean) * rstd * g1.w + be1.w);
    *(uint4*)(xn + row * DMD + lane * 8) = *(uint4*)o;
}

// ---------------- bf16 tensor-core GEMM ----------------
#define NSTG 3
#define PADK 72
#define TILE_B (128 * PADK * 2)
#define SMEM_G (2 * NSTG * TILE_B)     // 110592 B

__device__ __forceinline__ void ldsm4(uint32_t* r, uint32_t addr) {
    asm volatile("ldmatrix.sync.aligned.m8n8.x4.shared.b16 {%0,%1,%2,%3}, [%4];"
                 : "=r"(r[0]), "=r"(r[1]), "=r"(r[2]), "=r"(r[3]) : "r"(addr));
}
__device__ __forceinline__ void mma16816(float* d, const uint32_t* a, const uint32_t* b) {
    asm volatile(
        "mma.sync.aligned.m16n8k16.row.col.f32.bf16.bf16.f32 "
        "{%0,%1,%2,%3}, {%4,%5,%6,%7}, {%8,%9}, {%0,%1,%2,%3};\n"
        : "+f"(d[0]), "+f"(d[1]), "+f"(d[2]), "+f"(d[3])
        : "r"(a[0]), "r"(a[1]), "r"(a[2]), "r"(a[3]), "r"(b[0]), "r"(b[1]));
}

// EPI 0: GEMM1 -> n0<768: silu -> bf16 Cb (ld 2*DI); n0>=768: softplus fp32 -> Cd (ld DI)
// EPI 2: fp32 + resid -> Cf
template <int EPI>
__global__ void __launch_bounds__(512, 1)
bf_gemm(const __nv_bfloat16* __restrict__ A, int lda,
        const __nv_bfloat16* __restrict__ W, int ldb,
        const float* __restrict__ bias,
        float* __restrict__ Cf, int ldcf,
        __nv_bfloat16* __restrict__ Cb,
        float* __restrict__ Cd,
        int K,
        const float* __restrict__ resid)
{
    extern __shared__ char smem[];
    uint32_t sbA = smem_u32(smem);
    uint32_t sbB = sbA + NSTG * TILE_B;

    int tid = threadIdx.x, wid = tid >> 5, lane = tid & 31;
    int wm = wid & 3, wn = wid >> 2;
    int gid = lane >> 2, tig = lane & 3;
    int m0 = blockIdx.y * 128, n0 = blockIdx.x * 128;
    int KT = K / 64;

    const __nv_bfloat16* Ag = A + (long)m0 * lda;
    const __nv_bfloat16* Wg = W + (long)n0 * ldb;

    int lr0 = tid >> 3,          lk0 = (tid & 7) * 8;
    int lr1 = (tid + 512) >> 3,  lk1 = ((tid + 512) & 7) * 8;
    uint32_t so0 = (uint32_t)(lr0 * (PADK * 2) + lk0 * 2);
    uint32_t so1 = (uint32_t)(lr1 * (PADK * 2) + lk1 * 2);

    int arow = wm * 32 + (lane & 15);
    uint32_t aoff = (uint32_t)(arow * (PADK * 2) + ((lane >> 4) & 1) * 16);
    int grp = lane >> 3;
    int brow = wn * 32 + ((grp >> 1) * 8) + (lane & 7);
    uint32_t boff = (uint32_t)(brow * (PADK * 2) + (grp & 1) * 16);

    float acc[2][4][4];
    #pragma unroll
    for (int i = 0; i < 2; i++)
        #pragma unroll
        for (int j = 0; j < 4; j++)
            #pragma unroll
            for (int q = 0; q < 4; q++) acc[i][j][q] = 0.f;

    #pragma unroll
    for (int s = 0; s < NSTG - 1; s++) {
        cp16s(sbA + s * TILE_B + so0, Ag + (long)lr0 * lda + s * 64 + lk0);
        cp16s(sbA + s * TILE_B + so1, Ag + (long)lr1 * lda + s * 64 + lk1);
        cp16s(sbB + s * TILE_B + so0, Wg + (long)lr0 * ldb + s * 64 + lk0);
        cp16s(sbB + s * TILE_B + so1, Wg + (long)lr1 * ldb + s * 64 + lk1);
        cp_commit();
    }

    uint32_t af[2][2][4], bfr[2][4][2];

    for (int kt = 0; kt < KT; kt++) {
        asm volatile("cp.async.wait_group %0;" :: "n"(NSTG - 2));
        __syncthreads();

        int slot = kt % NSTG;
        uint32_t aS = sbA + slot * TILE_B;
        uint32_t bS = sbB + slot * TILE_B;

        {
            uint32_t t4[4];
            ldsm4(t4, bS + boff);
            bfr[0][0][0] = t4[0]; bfr[0][0][1] = t4[1];
            bfr[0][1][0] = t4[2]; bfr[0][1][1] = t4[3];
            ldsm4(t4, bS + boff + 16 * (PADK * 2));
            bfr[0][2][0] = t4[0]; bfr[0][2][1] = t4[1];
            bfr[0][3][0] = t4[2]; bfr[0][3][1] = t4[3];
            ldsm4(af[0][0], aS + aoff);
            ldsm4(af[0][1], aS + aoff + 16 * (PADK * 2));
        }

        int nk = kt + NSTG - 1;
        if (nk < KT) {
            int s = nk % NSTG;
            cp16s(sbA + s * TILE_B + so0, Ag + (long)lr0 * lda + nk * 64 + lk0);
            cp16s(sbA + s * TILE_B + so1, Ag + (long)lr1 * lda + nk * 64 + lk1);
            cp16s(sbB + s * TILE_B + so0, Wg + (long)lr0 * ldb + nk * 64 + lk0);
            cp16s(sbB + s * TILE_B + so1, Wg + (long)lr1 * ldb + nk * 64 + lk1);
        }
        cp_commit();

        #pragma unroll
        for (int kk = 0; kk < 4; kk++) {
            int cur = kk & 1, nxt = cur ^ 1;
            if (kk < 3) {
                int kb = (kk + 1) * 32;
                uint32_t t4[4];
                ldsm4(t4, bS + boff + kb);
                bfr[nxt][0][0] = t4[0]; bfr[nxt][0][1] = t4[1];
                bfr[nxt][1][0] = t4[2]; bfr[nxt][1][1] = t4[3];
                ldsm4(t4, bS + boff + 16 * (PADK * 2) + kb);
                bfr[nxt][2][0] = t4[0]; bfr[nxt][2][1] = t4[1];
                bfr[nxt][3][0] = t4[2]; bfr[nxt][3][1] = t4[3];
                ldsm4(af[nxt][0], aS + aoff + kb);
                ldsm4(af[nxt][1], aS + aoff + 16 * (PADK * 2) + kb);
            }
            #pragma unroll
            for (int ma = 0; ma < 2; ma++)
                #pragma unroll
                for (int na = 0; na < 4; na++)
                    mma16816(acc[ma][na], af[cur][ma], bfr[cur][na]);
        }
    }

    // epilogue
    bool dreg = (EPI == 0) && (n0 >= 2 * DI);
    #pragma unroll
    for (int ma = 0; ma < 2; ma++) {
        #pragma unroll
        for (int na = 0; na < 4; na++) {
            int col = n0 + wn * 32 + na * 8 + tig * 2;
            float b0 = bias[col], b1 = bias[col + 1];
            #pragma unroll
            for (int half = 0; half < 2; half++) {
                int row = m0 + wm * 32 + ma * 16 + gid + half * 8;
                float v0 = acc[ma][na][half * 2 + 0] + b0;
                float v1 = acc[ma][na][half * 2 + 1] + b1;
                if (EPI == 0) {
                    if (!dreg) {
                        v0 = v0 / (1.f + __expf(-v0));
                        v1 = v1 / (1.f + __expf(-v1));
                        __nv_bfloat162 o = __floats2bfloat162_rn(v0, v1);
                        *(__nv_bfloat162*)&Cb[(long)row * (2 * DI) + col] = o;
                    } else {
                        v0 = fmaxf(v0, 0.f) + log1pf(__expf(-fabsf(v0)));
                        v1 = fmaxf(v1, 0.f) + log1pf(__expf(-fabsf(v1)));
                        *(float2*)&Cd[(long)row * DI + (col - 2 * DI)] = make_float2(v0, v1);
                    }
                } else {
                    v0 += resid[(long)row * DMD + col];
                    v1 += resid[(long)row * DMD + col + 1];
                    *(float2*)&Cf[(long)row * ldcf + col] = make_float2(v0, v1);
                }
            }
        }
    }
}

// ---------------- chunked selective scan + gating ----------------
// 192 threads x 2 channels, explicit t+1 prefetch pipeline.
__global__ void __launch_bounds__(192)
scan_kernel(const __nv_bfloat16* __restrict__ xzb,
            const float* __restrict__ dt,
            const float* __restrict__ A_log,
            const float* __restrict__ D_vec,
            __nv_bfloat16* __restrict__ y)
{
    int p = threadIdx.x;           // channel pair index, 0..191
    int d0 = 2 * p;

    float av[2][DS];
    #pragma unroll
    for (int c = 0; c < 2; c++)
        #pragma unroll
        for (int s = 0; s < DS; s++)
            av[c][s] = -expf(A_log[(d0 + c) * DS + s]) * 1.4426950408889634f;
    float dv0 = D_vec[d0], dv1 = D_vec[d0 + 1];

    long row0 = (long)blockIdx.x * CHUNK;
    const float2*         dtp = (const float2*)(dt + row0 * DI) + p;
    const __nv_bfloat162* xp  = (const __nv_bfloat162*)(xzb + row0 * (2 * DI)) + p;
    const __nv_bfloat162* zp  = (const __nv_bfloat162*)(xzb + row0 * (2 * DI) + DI) + p;
    __nv_bfloat162*       yp  = (__nv_bfloat162*)(y + row0 * DI) + p;

    float h[2][DS];
    #pragma unroll
    for (int c = 0; c < 2; c++)
        #pragma unroll
        for (int s = 0; s < DS; s++) h[c][s] = 0.f;

    float2 dtv = *dtp;
    __nv_bfloat162 xv = *xp, zv = *zp;

    #pragma unroll 4
    for (int t = 0; t < CHUNK; t++) {
        float2 dtc = dtv;
        __nv_bfloat162 xc = xv, zc = zv;
        if (t + 1 < CHUNK) {
            dtv = dtp[(t + 1) * (DI / 2)];
            xv  = xp[(t + 1) * DI];       // row stride = 768 bf16 = 384 bf162 = DI
            zv  = zp[(t + 1) * DI];
        }
        float x0 = __bfloat162float(xc.x), x1 = __bfloat162float(xc.y);
        float z0 = __bfloat162float(zc.x), z1 = __bfloat162float(zc.y);
        float ys0 = 0.f, ys1 = 0.f;
        #pragma unroll
        for (int s = 0; s < DS; s++) {
            h[0][s] = fmaf(h[0][s], exp2f(dtc.x * av[0][s]), x0); ys0 += h[0][s];
            h[1][s] = fmaf(h[1][s], exp2f(dtc.y * av[1][s]), x1); ys1 += h[1][s];
        }
        __nv_bfloat162 o;
        o.x = __float2bfloat16(fmaf(ys0, z0, x0 * dv0));
        o.y = __float2bfloat16(fmaf(ys1, z1, x1 * dv1));
        yp[t * (DI / 2)] = o;
    }
}

// ---------------- launch ----------------
extern "C" void kernel_launch(void* const* d_in, const int* in_sizes, int n_in,
                              void* d_out, int out_size)
{
    const float* x     = (const float*)d_in[0];
    const float* gamma = (const float*)d_in[1];
    const float* beta  = (const float*)d_in[2];
    const float* W_in  = (const float*)d_in[3];
    const float* b_in  = (const float*)d_in[4];
    const float* W_dt  = (const float*)d_in[5];
    const float* b_dt  = (const float*)d_in[6];
    const float* A_log = (const float*)d_in[7];
    const float* D_vec = (const float*)d_in[8];
    const float* W_out = (const float*)d_in[9];
    const float* b_out = (const float*)d_in[10];
    float* out = (float*)d_out;

    __nv_bfloat16 *xn, *xzb, *yb, *wall, *wout;
    float *dtb, *ball;
    cudaGetSymbolAddress((void**)&xn,   g_xn);
    cudaGetSymbolAddress((void**)&xzb,  g_xzb);
    cudaGetSymbolAddress((void**)&dtb,  g_dt);
    cudaGetSymbolAddress((void**)&yb,   g_y);
    cudaGetSymbolAddress((void**)&wall, g_Wall);
    cudaGetSymbolAddress((void**)&ball, g_ball);
    cudaGetSymbolAddress((void**)&wout, g_Wout);

    cudaFuncSetAttribute(bf_gemm<0>, cudaFuncAttributeMaxDynamicSharedMemorySize, SMEM_G);
    cudaFuncSetAttribute(bf_gemm<2>, cudaFuncAttributeMaxDynamicSharedMemorySize, SMEM_G);

    // 0) prep
    cvt_w<<<(2 * DI * DMD + 255) / 256, 256>>>(W_in, W_out, b_in);
    wfuse_kernel<<<dim3(4, 6), 256>>>(W_dt, W_in);
    bfuse_kernel<<<DI, 128>>>(W_dt, b_in, b_dt);

    // 1) LayerNorm -> bf16
    ln_kernel<<<MTOK / 8, 256>>>(x, gamma, beta, xn);

    // 2) GEMM1: cols 0-767 -> silu bf16 xzb ; cols 768-1151 -> softplus fp32 dt
    bf_gemm<0><<<dim3(9, MTOK / 128), 512, SMEM_G>>>(
        xn, DMD, wall, DMD, ball, nullptr, 0, xzb, dtb, DMD, nullptr);

    // 3) chunked scan + gating -> y (bf16)
    scan_kernel<<<NCHUNK, 192>>>(xzb, dtb, A_log, D_vec, yb);

    // 4) GEMM3: out = y @ W_out^T + b_out + residual
    bf_gemm<2><<<dim3(2, MTOK / 128), 512, SMEM_G>>>(
        yb, DI, wout, DI, b_out, out, DMD, nullptr, nullptr, DI, x);
}

// round 12
// speedup vs baseline: 1.4507x; 1.0465x over previous
#include <cuda_runtime.h>
#include <cuda_bf16.h>
#include <cstdint>
#include <math.h>

#define BB   8
#define LL   4096
#define DMD  256
#define DI   384
#define DS   8
#define CHUNK 32
#define MTOK (BB*LL)          // 32768
#define NCHUNK (MTOK/CHUNK)   // 1024

// ---------------- scratch (device globals; no allocation) ----------------
__device__ __nv_bfloat16 g_xn  [MTOK * DMD];
__device__ __nv_bfloat16 g_xzb [MTOK * 2 * DI];   // bf16: silu(x_proj)|silu(z)
__device__ float         g_dt  [MTOK * DI];       // softplus(dt) fp32
__device__ __nv_bfloat16 g_y   [MTOK * DI];
__device__ __nv_bfloat16 g_Wall[3 * DI * DMD];    // rows 0-767: Win[0:768]; 768-1151: W_fused
__device__ float         g_ball[3 * DI];          // b_in[0:768] | b_fused
__device__ __nv_bfloat16 g_Wout[DMD * DI];

// ---------------- helpers ----------------
__device__ __forceinline__ uint32_t smem_u32(const void* p) {
    uint32_t a;
    asm("{ .reg .u64 t; cvta.to.shared.u64 t, %1; cvt.u32.u64 %0, t; }" : "=r"(a) : "l"(p));
    return a;
}
__device__ __forceinline__ void cp16s(uint32_t s, const void* g) {
    asm volatile("cp.async.cg.shared.global [%0], [%1], 16;\n" :: "r"(s), "l"(g));
}
__device__ __forceinline__ void cp_commit() { asm volatile("cp.async.commit_group;\n"); }

// ---------------- fused front-end: LN + weight prep, one kernel ----------------
// blocks [0,4096): LN (8 rows each)
// blocks [4096,4864): copy/convert Win[0:768], Wout, b_in
// blocks [4864,4888): wfuse (W_fused = Wdt @ Win[768:1152])
// blocks [4888,5272): bfuse (b_fused = Wdt @ b_in[768:1152] + b_dt)
#define NB_LN   4096
#define NB_CVT  768
#define NB_WF   24
#define NB_BF   384
#define NB_PRE  (NB_LN + NB_CVT + NB_WF + NB_BF)

__global__ void __launch_bounds__(256)
pre_kernel(const float* __restrict__ x,
           const float* __restrict__ gamma,
           const float* __restrict__ beta,
           const float* __restrict__ Win,
           const float* __restrict__ Wdt,
           const float* __restrict__ b_in,
           const float* __restrict__ b_dt,
           const float* __restrict__ Wout,
           __nv_bfloat16* __restrict__ xn)
{
    int b = blockIdx.x;
    int tid = threadIdx.x;

    if (b < NB_LN) {
        // ---- LayerNorm, warp per row ----
        int warp = tid >> 5, lane = tid & 31;
        long row = (long)b * 8 + warp;
        const float* xr = x + row * DMD;

        float4 v0 = *(const float4*)(xr + lane * 8);
        float4 v1 = *(const float4*)(xr + lane * 8 + 4);

        float s1 = v0.x + v0.y + v0.z + v0.w + v1.x + v1.y + v1.z + v1.w;
        float s2 = v0.x*v0.x + v0.y*v0.y + v0.z*v0.z + v0.w*v0.w
                 + v1.x*v1.x + v1.y*v1.y + v1.z*v1.z + v1.w*v1.w;
        #pragma unroll
        for (int o = 16; o; o >>= 1) {
            s1 += __shfl_xor_sync(0xffffffffu, s1, o);
            s2 += __shfl_xor_sync(0xffffffffu, s2, o);
        }
        float mean = s1 * (1.0f / DMD);
        float rstd = rsqrtf(s2 * (1.0f / DMD) - mean * mean + 1e-5f);

        const float4 g0 = *(const float4*)(gamma + lane * 8);
        const float4 g1 = *(const float4*)(gamma + lane * 8 + 4);
        const float4 be0 = *(const float4*)(beta + lane * 8);
        const float4 be1 = *(const float4*)(beta + lane * 8 + 4);

        __nv_bfloat16 o[8];
        o[0] = __float2bfloat16((v0.x - mean) * rstd * g0.x + be0.x);
        o[1] = __float2bfloat16((v0.y - mean) * rstd * g0.y + be0.y);
        o[2] = __float2bfloat16((v0.z - mean) * rstd * g0.z + be0.z);
        o[3] = __float2bfloat16((v0.w - mean) * rstd * g0.w + be0.w);
        o[4] = __float2bfloat16((v1.x - mean) * rstd * g1.x + be1.x);
        o[5] = __float2bfloat16((v1.y - mean) * rstd * g1.y + be1.y);
        o[6] = __float2bfloat16((v1.z - mean) * rstd * g1.z + be1.z);
        o[7] = __float2bfloat16((v1.w - mean) * rstd * g1.w + be1.w);
        *(uint4*)(xn + row * DMD + lane * 8) = *(uint4*)o;
    } else if (b < NB_LN + NB_CVT) {
        // ---- copy/convert ----
        int i = (b - NB_LN) * 256 + tid;
        if (i < 2 * DI * DMD) g_Wall[i] = __float2bfloat16(Win[i]);
        if (i < DMD * DI)     g_Wout[i] = __float2bfloat16(Wout[i]);
        if (i < 2 * DI)       g_ball[i] = b_in[i];
    } else if (b < NB_LN + NB_CVT + NB_WF) {
        // ---- wfuse: W_fused = Wdt @ Win[768:1152] ----
        __shared__ float As[64][17];
        __shared__ float Bs[16][65];
        int bb = b - NB_LN - NB_CVT;
        int bx = bb & 3, by = bb >> 2;     // 4 x 6
        int ty = tid >> 4, tx = tid & 15;
        float acc[4][4] = {};

        for (int kt = 0; kt < DI; kt += 16) {
            {
                int r = tid >> 2, c4 = (tid & 3) * 4;
                float4 v = *(const float4*)&Wdt[(by * 64 + r) * DI + kt + c4];
                As[r][c4] = v.x; As[r][c4 + 1] = v.y; As[r][c4 + 2] = v.z; As[r][c4 + 3] = v.w;
            }
            {
                int r = tid >> 4, c4 = (tid & 15) * 4;
                float4 v = *(const float4*)&Win[(2 * DI + kt + r) * DMD + bx * 64 + c4];
                Bs[r][c4] = v.x; Bs[r][c4 + 1] = v.y; Bs[r][c4 + 2] = v.z; Bs[r][c4 + 3] = v.w;
            }
            __syncthreads();
            #pragma unroll
            for (int k = 0; k < 16; k++) {
                float a[4], bv[4];
                #pragma unroll
                for (int i = 0; i < 4; i++) a[i] = As[ty * 4 + i][k];
                #pragma unroll
                for (int j = 0; j < 4; j++) bv[j] = Bs[k][tx * 4 + j];
                #pragma unroll
                for (int i = 0; i < 4; i++)
                    #pragma unroll
                    for (int j = 0; j < 4; j++) acc[i][j] = fmaf(a[i], bv[j], acc[i][j]);
            }
            __syncthreads();
        }
        #pragma unroll
        for (int i = 0; i < 4; i++)
            #pragma unroll
            for (int j = 0; j < 4; j++)
                g_Wall[(2 * DI + by * 64 + ty * 4 + i) * DMD + bx * 64 + tx * 4 + j] =
                    __float2bfloat16(acc[i][j]);
    } else {
        // ---- bfuse: row dot product ----
        int i = b - NB_LN - NB_CVT - NB_WF;    // 0..383
        float s = 0.f;
        for (int j = tid; j < DI; j += 256)
            s = fmaf(Wdt[i * DI + j], b_in[2 * DI + j], s);
        #pragma unroll
        for (int o = 16; o; o >>= 1) s += __shfl_xor_sync(0xffffffffu, s, o);
        __shared__ float red[8];
        if ((tid & 31) == 0) red[tid >> 5] = s;
        __syncthreads();
        if (tid == 0) {
            float t = 0.f;
            #pragma unroll
            for (int w = 0; w < 8; w++) t += red[w];
            g_ball[2 * DI + i] = t + b_dt[i];
        }
    }
}

// ---------------- bf16 tensor-core GEMM ----------------
#define NSTG 3
#define PADK 72
#define TILE_B (128 * PADK * 2)
#define SMEM_G (2 * NSTG * TILE_B)     // 110592 B

__device__ __forceinline__ void ldsm4(uint32_t* r, uint32_t addr) {
    asm volatile("ldmatrix.sync.aligned.m8n8.x4.shared.b16 {%0,%1,%2,%3}, [%4];"
                 : "=r"(r[0]), "=r"(r[1]), "=r"(r[2]), "=r"(r[3]) : "r"(addr));
}
__device__ __forceinline__ void mma16816(float* d, const uint32_t* a, const uint32_t* b) {
    asm volatile(
        "mma.sync.aligned.m16n8k16.row.col.f32.bf16.bf16.f32 "
        "{%0,%1,%2,%3}, {%4,%5,%6,%7}, {%8,%9}, {%0,%1,%2,%3};\n"
        : "+f"(d[0]), "+f"(d[1]), "+f"(d[2]), "+f"(d[3])
        : "r"(a[0]), "r"(a[1]), "r"(a[2]), "r"(a[3]), "r"(b[0]), "r"(b[1]));
}

// EPI 0: GEMM1 -> n0<768: silu -> bf16 Cb; n0>=768: softplus fp32 -> Cd
// EPI 2: fp32 + resid -> Cf
template <int EPI>
__global__ void __launch_bounds__(512, 1)
bf_gemm(const __nv_bfloat16* __restrict__ A, int lda,
        const __nv_bfloat16* __restrict__ W, int ldb,
        const float* __restrict__ bias,
        float* __restrict__ Cf, int ldcf,
        __nv_bfloat16* __restrict__ Cb,
        float* __restrict__ Cd,
        int K,
        const float* __restrict__ resid)
{
    extern __shared__ char smem[];
    uint32_t sbA = smem_u32(smem);
    uint32_t sbB = sbA + NSTG * TILE_B;

    int tid = threadIdx.x, wid = tid >> 5, lane = tid & 31;
    int wm = wid & 3, wn = wid >> 2;
    int gid = lane >> 2, tig = lane & 3;
    int m0 = blockIdx.y * 128, n0 = blockIdx.x * 128;
    int KT = K / 64;

    const __nv_bfloat16* Ag = A + (long)m0 * lda;
    const __nv_bfloat16* Wg = W + (long)n0 * ldb;

    int lr0 = tid >> 3,          lk0 = (tid & 7) * 8;
    int lr1 = (tid + 512) >> 3,  lk1 = ((tid + 512) & 7) * 8;
    uint32_t so0 = (uint32_t)(lr0 * (PADK * 2) + lk0 * 2);
    uint32_t so1 = (uint32_t)(lr1 * (PADK * 2) + lk1 * 2);

    int arow = wm * 32 + (lane & 15);
    uint32_t aoff = (uint32_t)(arow * (PADK * 2) + ((lane >> 4) & 1) * 16);
    int grp = lane >> 3;
    int brow = wn * 32 + ((grp >> 1) * 8) + (lane & 7);
    uint32_t boff = (uint32_t)(brow * (PADK * 2) + (grp & 1) * 16);

    float acc[2][4][4];
    #pragma unroll
    for (int i = 0; i < 2; i++)
        #pragma unroll
        for (int j = 0; j < 4; j++)
            #pragma unroll
            for (int q = 0; q < 4; q++) acc[i][j][q] = 0.f;

    #pragma unroll
    for (int s = 0; s < NSTG - 1; s++) {
        cp16s(sbA + s * TILE_B + so0, Ag + (long)lr0 * lda + s * 64 + lk0);
        cp16s(sbA + s * TILE_B + so1, Ag + (long)lr1 * lda + s * 64 + lk1);
        cp16s(sbB + s * TILE_B + so0, Wg + (long)lr0 * ldb + s * 64 + lk0);
        cp16s(sbB + s * TILE_B + so1, Wg + (long)lr1 * ldb + s * 64 + lk1);
        cp_commit();
    }

    uint32_t af[2][2][4], bfr[2][4][2];

    for (int kt = 0; kt < KT; kt++) {
        asm volatile("cp.async.wait_group %0;" :: "n"(NSTG - 2));
        __syncthreads();

        int slot = kt % NSTG;
        uint32_t aS = sbA + slot * TILE_B;
        uint32_t bS = sbB + slot * TILE_B;

        {
            uint32_t t4[4];
            ldsm4(t4, bS + boff);
            bfr[0][0][0] = t4[0]; bfr[0][0][1] = t4[1];
            bfr[0][1][0] = t4[2]; bfr[0][1][1] = t4[3];
            ldsm4(t4, bS + boff + 16 * (PADK * 2));
            bfr[0][2][0] = t4[0]; bfr[0][2][1] = t4[1];
            bfr[0][3][0] = t4[2]; bfr[0][3][1] = t4[3];
            ldsm4(af[0][0], aS + aoff);
            ldsm4(af[0][1], aS + aoff + 16 * (PADK * 2));
        }

        int nk = kt + NSTG - 1;
        if (nk < KT) {
            int s = nk % NSTG;
            cp16s(sbA + s * TILE_B + so0, Ag + (long)lr0 * lda + nk * 64 + lk0);
            cp16s(sbA + s * TILE_B + so1, Ag + (long)lr1 * lda + nk * 64 + lk1);
            cp16s(sbB + s * TILE_B + so0, Wg + (long)lr0 * ldb + nk * 64 + lk0);
            cp16s(sbB + s * TILE_B + so1, Wg + (long)lr1 * ldb + nk * 64 + lk1);
        }
        cp_commit();

        #pragma unroll
        for (int kk = 0; kk < 4; kk++) {
            int cur = kk & 1, nxt = cur ^ 1;
            if (kk < 3) {
                int kb = (kk + 1) * 32;
                uint32_t t4[4];
                ldsm4(t4, bS + boff + kb);
                bfr[nxt][0][0] = t4[0]; bfr[nxt][0][1] = t4[1];
                bfr[nxt][1][0] = t4[2]; bfr[nxt][1][1] = t4[3];
                ldsm4(t4, bS + boff + 16 * (PADK * 2) + kb);
                bfr[nxt][2][0] = t4[0]; bfr[nxt][2][1] = t4[1];
                bfr[nxt][3][0] = t4[2]; bfr[nxt][3][1] = t4[3];
                ldsm4(af[nxt][0], aS + aoff + kb);
                ldsm4(af[nxt][1], aS + aoff + 16 * (PADK * 2) + kb);
            }
            #pragma unroll
            for (int ma = 0; ma < 2; ma++)
                #pragma unroll
                for (int na = 0; na < 4; na++)
                    mma16816(acc[ma][na], af[cur][ma], bfr[cur][na]);
        }
    }

    // epilogue
    bool dreg = (EPI == 0) && (n0 >= 2 * DI);
    #pragma unroll
    for (int ma = 0; ma < 2; ma++) {
        #pragma unroll
        for (int na = 0; na < 4; na++) {
            int col = n0 + wn * 32 + na * 8 + tig * 2;
            float b0 = bias[col], b1 = bias[col + 1];
            #pragma unroll
            for (int half = 0; half < 2; half++) {
                int row = m0 + wm * 32 + ma * 16 + gid + half * 8;
                float v0 = acc[ma][na][half * 2 + 0] + b0;
                float v1 = acc[ma][na][half * 2 + 1] + b1;
                if (EPI == 0) {
                    if (!dreg) {
                        v0 = v0 / (1.f + __expf(-v0));
                        v1 = v1 / (1.f + __expf(-v1));
                        __nv_bfloat162 o = __floats2bfloat162_rn(v0, v1);
                        *(__nv_bfloat162*)&Cb[(long)row * (2 * DI) + col] = o;
                    } else {
                        v0 = fmaxf(v0, 0.f) + log1pf(__expf(-fabsf(v0)));
                        v1 = fmaxf(v1, 0.f) + log1pf(__expf(-fabsf(v1)));
                        *(float2*)&Cd[(long)row * DI + (col - 2 * DI)] = make_float2(v0, v1);
                    }
                } else {
                    v0 += resid[(long)row * DMD + col];
                    v1 += resid[(long)row * DMD + col + 1];
                    *(float2*)&Cf[(long)row * ldcf + col] = make_float2(v0, v1);
                }
            }
        }
    }
}

// ---------------- chunked selective scan + gating ----------------
// 512 blocks; each thread: 2 channels x 2 chunks, prefetch pipeline (12 loads in flight).
__global__ void __launch_bounds__(192)
scan_kernel(const __nv_bfloat16* __restrict__ xzb,
            const float* __restrict__ dt,
            const float* __restrict__ A_log,
            const float* __restrict__ D_vec,
            __nv_bfloat16* __restrict__ y)
{
    int p = threadIdx.x;           // channel-pair index 0..191
    int d0 = 2 * p;

    float av[2][DS];
    #pragma unroll
    for (int c = 0; c < 2; c++)
        #pragma unroll
        for (int s = 0; s < DS; s++)
            av[c][s] = -expf(A_log[(d0 + c) * DS + s]) * 1.4426950408889634f;
    float dv0 = D_vec[d0], dv1 = D_vec[d0 + 1];

    long rowA = (long)blockIdx.x * 2 * CHUNK;        // chunk pair
    long rowB = rowA + CHUNK;

    const float2*         dtA = (const float2*)(dt + rowA * DI) + p;
    const __nv_bfloat162* xA  = (const __nv_bfloat162*)(xzb + rowA * (2 * DI)) + p;
    const __nv_bfloat162* zA  = (const __nv_bfloat162*)(xzb + rowA * (2 * DI) + DI) + p;
    __nv_bfloat162*       yA  = (__nv_bfloat162*)(y + rowA * DI) + p;
    const float2*         dtB = (const float2*)(dt + rowB * DI) + p;
    const __nv_bfloat162* xB  = (const __nv_bfloat162*)(xzb + rowB * (2 * DI)) + p;
    const __nv_bfloat162* zB  = (const __nv_bfloat162*)(xzb + rowB * (2 * DI) + DI) + p;
    __nv_bfloat162*       yB  = (__nv_bfloat162*)(y + rowB * DI) + p;

    float h[2][2][DS];
    #pragma unroll
    for (int q = 0; q < 2; q++)
        #pragma unroll
        for (int c = 0; c < 2; c++)
            #pragma unroll
            for (int s = 0; s < DS; s++) h[q][c][s] = 0.f;

    float2 dtvA = *dtA, dtvB = *dtB;
    __nv_bfloat162 xvA = *xA, zvA = *zA, xvB = *xB, zvB = *zB;

    #pragma unroll 2
    for (int t = 0; t < CHUNK; t++) {
        float2 dA = dtvA, dB = dtvB;
        __nv_bfloat162 xa = xvA, za = zvA, xb = xvB, zb = zvB;
        if (t + 1 < CHUNK) {
            dtvA = dtA[(t + 1) * (DI / 2)];
            xvA  = xA[(t + 1) * DI];
            zvA  = zA[(t + 1) * DI];
            dtvB = dtB[(t + 1) * (DI / 2)];
            xvB  = xB[(t + 1) * DI];
            zvB  = zB[(t + 1) * DI];
        }
        // chunk A
        {
            float x0 = __bfloat162float(xa.x), x1 = __bfloat162float(xa.y);
            float z0 = __bfloat162float(za.x), z1 = __bfloat162float(za.y);
            float ys0 = 0.f, ys1 = 0.f;
            #pragma unroll
            for (int s = 0; s < DS; s++) {
                h[0][0][s] = fmaf(h[0][0][s], exp2f(dA.x * av[0][s]), x0); ys0 += h[0][0][s];
                h[0][1][s] = fmaf(h[0][1][s], exp2f(dA.y * av[1][s]), x1); ys1 += h[0][1][s];
            }
            __nv_bfloat162 o;
            o.x = __float2bfloat16(fmaf(ys0, z0, x0 * dv0));
            o.y = __float2bfloat16(fmaf(ys1, z1, x1 * dv1));
            yA[t * (DI / 2)] = o;
        }
        // chunk B
        {
            float x0 = __bfloat162float(xb.x), x1 = __bfloat162float(xb.y);
            float z0 = __bfloat162float(zb.x), z1 = __bfloat162float(zb.y);
            float ys0 = 0.f, ys1 = 0.f;
            #pragma unroll
            for (int s = 0; s < DS; s++) {
                h[1][0][s] = fmaf(h[1][0][s], exp2f(dB.x * av[0][s]), x0); ys0 += h[1][0][s];
                h[1][1][s] = fmaf(h[1][1][s], exp2f(dB.y * av[1][s]), x1); ys1 += h[1][1][s];
            }
            __nv_bfloat162 o;
            o.x = __float2bfloat16(fmaf(ys0, z0, x0 * dv0));
            o.y = __float2bfloat16(fmaf(ys1, z1, x1 * dv1));
            yB[t * (DI / 2)] = o;
        }
    }
}

// ---------------- launch ----------------
extern "C" void kernel_launch(void* const* d_in, const int* in_sizes, int n_in,
                              void* d_out, int out_size)
{
    const float* x     = (const float*)d_in[0];
    const float* gamma = (const float*)d_in[1];
    const float* beta  = (const float*)d_in[2];
    const float* W_in  = (const float*)d_in[3];
    const float* b_in  = (const float*)d_in[4];
    const float* W_dt  = (const float*)d_in[5];
    const float* b_dt  = (const float*)d_in[6];
    const float* A_log = (const float*)d_in[7];
    const float* D_vec = (const float*)d_in[8];
    const float* W_out = (const float*)d_in[9];
    const float* b_out = (const float*)d_in[10];
    float* out = (float*)d_out;

    __nv_bfloat16 *xn, *xzb, *yb, *wall, *wout;
    float *dtb, *ball;
    cudaGetSymbolAddress((void**)&xn,   g_xn);
    cudaGetSymbolAddress((void**)&xzb,  g_xzb);
    cudaGetSymbolAddress((void**)&dtb,  g_dt);
    cudaGetSymbolAddress((void**)&yb,   g_y);
    cudaGetSymbolAddress((void**)&wall, g_Wall);
    cudaGetSymbolAddress((void**)&ball, g_ball);
    cudaGetSymbolAddress((void**)&wout, g_Wout);

    cudaFuncSetAttribute(bf_gemm<0>, cudaFuncAttributeMaxDynamicSharedMemorySize, SMEM_G);
    cudaFuncSetAttribute(bf_gemm<2>, cudaFuncAttributeMaxDynamicSharedMemorySize, SMEM_G);

    // 1) fused front-end: LN + all weight prep, one kernel
    pre_kernel<<<NB_PRE, 256>>>(x, gamma, beta, W_in, W_dt, b_in, b_dt, W_out, xn);

    // 2) GEMM1: cols 0-767 -> silu bf16 xzb ; cols 768-1151 -> softplus fp32 dt
    bf_gemm<0><<<dim3(9, MTOK / 128), 512, SMEM_G>>>(
        xn, DMD, wall, DMD, ball, nullptr, 0, xzb, dtb, DMD, nullptr);

    // 3) chunked scan + gating -> y (bf16), 2 chunks/thread
    scan_kernel<<<NCHUNK / 2, 192>>>(xzb, dtb, A_log, D_vec, yb);

    // 4) GEMM3: out = y @ W_out^T + b_out + residual
    bf_gemm<2><<<dim3(2, MTOK / 128), 512, SMEM_G>>>(
        yb, DI, wout, DI, b_out, out, DMD, nullptr, nullptr, DI, x);
}